// round 1
// baseline (speedup 1.0000x reference)
#include <cuda_runtime.h>

// IntShear4: M = S_{11} @ ... @ S_0, S_p = I + k_int[p] * e_{i_p} e_{j_p}^T
// k_int = round(3 * tanh(k_raw))  (round-half-even, matching jnp.round)
// Left-multiplying by a shear is: row_i += k * row_j. 12 pairs, 4x4 fp32 out.
__global__ void intshear4_kernel(const float* __restrict__ k_raw,
                                 const int* __restrict__ pairs_i,
                                 const int* __restrict__ pairs_j,
                                 float* __restrict__ out,
                                 int P) {
    if (threadIdx.x != 0) return;

    // M starts as identity, kept in local array (registers/local).
    float M[4][4];
#pragma unroll
    for (int r = 0; r < 4; r++)
#pragma unroll
        for (int c = 0; c < 4; c++)
            M[r][c] = (r == c) ? 1.0f : 0.0f;

    for (int p = 0; p < P; p++) {
        float k = rintf(3.0f * tanhf(k_raw[p]));  // rintf = round-half-even
        int i = pairs_i[p];
        int j = pairs_j[p];
#pragma unroll
        for (int c = 0; c < 4; c++)
            M[i][c] = fmaf(k, M[j][c], M[i][c]);
    }

#pragma unroll
    for (int r = 0; r < 4; r++)
#pragma unroll
        for (int c = 0; c < 4; c++)
            out[r * 4 + c] = M[r][c];
}

extern "C" void kernel_launch(void* const* d_in, const int* in_sizes, int n_in,
                              void* d_out, int out_size) {
    const float* k_raw   = (const float*)d_in[0];
    const int*   pairs_i = (const int*)d_in[1];
    const int*   pairs_j = (const int*)d_in[2];
    float* out = (float*)d_out;
    int P = in_sizes[0];
    intshear4_kernel<<<1, 32>>>(k_raw, pairs_i, pairs_j, out, P);
}

// round 2
// speedup vs baseline: 1.0052x; 1.0052x over previous
#include <cuda_runtime.h>

// IntShear4: M = S_{P-1} @ ... @ S_0, S_p = I + k_int[p] * e_i e_j^T
// k_int = round-half-even(3 * tanh(k_raw)).
// Left shear == row_i(M) += k * row_j(M): columns of M evolve independently.
//
// Phase 1 (lanes 0..P-1, parallel): load triple, compute k_int, stash in smem.
// Phase 2 (lanes 0..3, parallel over columns): serial 12-step chain, each lane
// holds one full column of M in registers.
#define P_MAX 16

__global__ void intshear4_kernel(const float* __restrict__ k_raw,
                                 const int* __restrict__ pairs_i,
                                 const int* __restrict__ pairs_j,
                                 float* __restrict__ out,
                                 int P) {
    __shared__ float sk[P_MAX];
    __shared__ int   si[P_MAX];
    __shared__ int   sj[P_MAX];

    int lane = threadIdx.x;

    // Phase 1: parallel load + tanh (one memory round-trip for everything)
    if (lane < P) {
        float kr = k_raw[lane];
        int   ii = pairs_i[lane];
        int   jj = pairs_j[lane];
        sk[lane] = rintf(3.0f * tanhf(kr));   // rintf = round-half-even
        si[lane] = ii;
        sj[lane] = jj;
    }
    __syncwarp();

    // Phase 2: lanes 0..3 each own column `lane` of M (rows m0..m3)
    if (lane < 4) {
        float m0 = (lane == 0) ? 1.0f : 0.0f;
        float m1 = (lane == 1) ? 1.0f : 0.0f;
        float m2 = (lane == 2) ? 1.0f : 0.0f;
        float m3 = (lane == 3) ? 1.0f : 0.0f;

        for (int p = 0; p < P; p++) {
            float kk = sk[p];
            int   ii = si[p];
            int   jj = sj[p];
            float src = (jj == 0) ? m0 : (jj == 1) ? m1 : (jj == 2) ? m2 : m3;
            float add = kk * src;
            if      (ii == 0) m0 += add;
            else if (ii == 1) m1 += add;
            else if (ii == 2) m2 += add;
            else              m3 += add;
        }

        // out is row-major [4,4]; lane = column index
        out[0 * 4 + lane] = m0;
        out[1 * 4 + lane] = m1;
        out[2 * 4 + lane] = m2;
        out[3 * 4 + lane] = m3;
    }
}

extern "C" void kernel_launch(void* const* d_in, const int* in_sizes, int n_in,
                              void* d_out, int out_size) {
    const float* k_raw   = (const float*)d_in[0];
    const int*   pairs_i = (const int*)d_in[1];
    const int*   pairs_j = (const int*)d_in[2];
    float* out = (float*)d_out;
    int P = in_sizes[0];
    intshear4_kernel<<<1, 32>>>(k_raw, pairs_i, pairs_j, out, P);
}

// round 3
// speedup vs baseline: 1.0104x; 1.0052x over previous
#include <cuda_runtime.h>

// IntShear4: M = S_{P-1} @ ... @ S_0, S_p = I + k_int[p] * e_i e_j^T
// k_int = round-half-even(3 * tanh(k_raw)).
// Left shear == row_i(M) += k * row_j(M): columns of M evolve independently.
//
// Phase 1 (lanes 0..P-1): load triple, k_int = rintf(3*tanhf(k)),
//   pack (i,j) as code = i*4+j, stash (k, code) in smem.
// Phase 2 (lanes 0..3): each lane owns one column of M in registers and runs
//   the fully-unrolled 12-step chain (P==12 specialized so all LDS are
//   hoisted ahead of the dependent FMA chain).
#define P_MAX 16

__global__ void intshear4_kernel(const float* __restrict__ k_raw,
                                 const int* __restrict__ pairs_i,
                                 const int* __restrict__ pairs_j,
                                 float* __restrict__ out,
                                 int P) {
    __shared__ float sk[P_MAX];
    __shared__ int   sc[P_MAX];

    int lane = threadIdx.x;

    if (lane < P) {
        float kr = k_raw[lane];
        int   ii = pairs_i[lane];
        int   jj = pairs_j[lane];
        sk[lane] = rintf(3.0f * tanhf(kr));   // rintf = round-half-even
        sc[lane] = ii * 4 + jj;
    }
    __syncwarp();

    if (lane < 4) {
        float m0 = (lane == 0) ? 1.0f : 0.0f;
        float m1 = (lane == 1) ? 1.0f : 0.0f;
        float m2 = (lane == 2) ? 1.0f : 0.0f;
        float m3 = (lane == 3) ? 1.0f : 0.0f;

        if (P == 12) {
#pragma unroll
            for (int p = 0; p < 12; p++) {
                float kk   = sk[p];
                int   code = sc[p];
                int   jj   = code & 3;
                int   ii   = code >> 2;
                float src = (jj == 0) ? m0 : (jj == 1) ? m1 : (jj == 2) ? m2 : m3;
                float add = kk * src;
                if      (ii == 0) m0 += add;
                else if (ii == 1) m1 += add;
                else if (ii == 2) m2 += add;
                else              m3 += add;
            }
        } else {
            for (int p = 0; p < P; p++) {
                float kk   = sk[p];
                int   code = sc[p];
                int   jj   = code & 3;
                int   ii   = code >> 2;
                float src = (jj == 0) ? m0 : (jj == 1) ? m1 : (jj == 2) ? m2 : m3;
                float add = kk * src;
                if      (ii == 0) m0 += add;
                else if (ii == 1) m1 += add;
                else if (ii == 2) m2 += add;
                else              m3 += add;
            }
        }

        // out is row-major [4,4]; lane = column index
        out[0 * 4 + lane] = m0;
        out[1 * 4 + lane] = m1;
        out[2 * 4 + lane] = m2;
        out[3 * 4 + lane] = m3;
    }
}

extern "C" void kernel_launch(void* const* d_in, const int* in_sizes, int n_in,
                              void* d_out, int out_size) {
    const float* k_raw   = (const float*)d_in[0];
    const int*   pairs_i = (const int*)d_in[1];
    const int*   pairs_j = (const int*)d_in[2];
    float* out = (float*)d_out;
    int P = in_sizes[0];
    intshear4_kernel<<<1, 32>>>(k_raw, pairs_i, pairs_j, out, P);
}